// round 9
// baseline (speedup 1.0000x reference)
#include <cuda_runtime.h>

// ---------------------------------------------------------------------------
// IPB windowed inhibition attention, fp32. Round 9:
//  - softmax restructured: 8 lanes per row, shfl.xor(1,2,4) group reductions
//    (640 -> 96 warp-SHFL per CTA); redux.f32 does not exist on sm_103
//  - small weight vectors in __constant__ (uniform LDCU, off l1tex)
//  - S6 at 8 tokens x 4 dims per thread
//  - prep kernel: permuted W^T (S1 float4 w-loads), W_vo = W_out@W_v, W_m2a^T
// One CTA per (window, B): 8192 CTAs x 256 threads, 4 CTAs/SM.
// ---------------------------------------------------------------------------

#define TPB 256

namespace {
constexpr int H_STR = 256 * 28;
constexpr int B_STR = 256 * 256 * 28;

constexpr int STS = 68;   // stride for ssim / satT
constexpr int STW = 84;   // stride for sWT [28][84] (permuted cols)

constexpr int OFF_XT  = 0;      // [28][64]
constexpr int OFF_QT  = 1792;   // [28][64] swizzled
constexpr int OFF_KT  = 3584;   // [28][64] swizzled
constexpr int OFF_AT  = 0;      // attnT [64][68] alias (region A reuse)
constexpr int OFF_WT  = 5376;   // [28][84] permuted: c' = 4*(c%21) + c/21
constexpr int OFF_V   = 7728;   // V' [64][28]
constexpr int OFF_SIM = 9520;   // [64][68]
constexpr int OFF_SGQ = 13872;
constexpr int OFF_SGK = 13936;
constexpr int OFF_TH  = 14000;
constexpr int OFF_RED = 14064;
constexpr int SM_FLOATS = 14068;
constexpr int SM_BYTES  = SM_FLOATS * 4;   // 56272 B -> 4 CTAs/SM
}

// prepared weights (written by prep_kernel)
__device__ __align__(16) float g_WT[28 * 84];      // [k][c']: permuted W_qk^T|W_vo^T
__device__ __align__(16) float g_Wm2aT[64 * 64];   // [j][i]

// small weights in constant bank
__constant__ __align__(16) float c_Wm1[64];
__constant__ __align__(16) float c_Wm2b[64];
__constant__ __align__(16) float c_Wpcq[28];
__constant__ __align__(16) float c_Wpck[28];
__constant__ __align__(16) float c_bout[28];
__constant__ float c_bpcq[1];
__constant__ float c_bpck[1];

__global__ void __launch_bounds__(TPB) prep_kernel(
    const float* __restrict__ W_qk,   // [56,28]
    const float* __restrict__ W_v,    // [28,28]
    const float* __restrict__ W_out,  // [28,28]
    const float* __restrict__ W_m2a)  // [64,64]
{
    const int gtid = blockIdx.x * TPB + threadIdx.x;
    const int gstep = gridDim.x * TPB;
    for (int i = gtid; i < 1568; i += gstep) {
        const int c = i % 56, k = i / 56;
        const int cp = 4 * (c % 21) + (c / 21);
        g_WT[k * STW + cp] = W_qk[c * 28 + k];
    }
    for (int i = gtid; i < 784; i += gstep) {
        const int c = i / 28, e = i % 28;
        float acc = 0.f;
        #pragma unroll 7
        for (int d = 0; d < 28; d++)
            acc = fmaf(W_out[c * 28 + d], W_v[d * 28 + e], acc);
        const int lc = 56 + c;
        const int cp = 4 * (lc % 21) + (lc / 21);
        g_WT[e * STW + cp] = acc;
    }
    for (int i = gtid; i < 4096; i += gstep) {
        const int r = i >> 6, cc = i & 63;
        g_Wm2aT[cc * 64 + r] = W_m2a[i];
    }
}

__global__ void __launch_bounds__(TPB, 4) ipb_kernel(
    const float* __restrict__ x,
    float* __restrict__ out)
{
    extern __shared__ float sm[];
    float* sxT  = sm + OFF_XT;
    float* sqT  = sm + OFF_QT;
    float* skT  = sm + OFF_KT;
    float* satT = sm + OFF_AT;
    float* sWT  = sm + OFF_WT;
    float* sv   = sm + OFF_V;
    float* ssim = sm + OFF_SIM;
    float* sigq = sm + OFF_SGQ;
    float* sigk = sm + OFF_SGK;
    float* sth  = sm + OFF_TH;
    float* sred = sm + OFF_RED;

    const int tid  = threadIdx.x;
    const int widx = blockIdx.x & 1023;
    const int Bi   = blockIdx.x >> 10;
    const int wh = widx >> 5, ww = widx & 31;
    const float* xbase = x + (size_t)Bi * B_STR + wh * 8 * H_STR + ww * 8 * 28;

    // ======== S0: x transpose + prepared-weight copy ========
    {
        {
            const int r = tid & 63, c4 = (tid >> 6) * 4;
            const float4 v = *(const float4*)(xbase + (r >> 3) * H_STR + (r & 7) * 28 + c4);
            sxT[(c4 + 0) * 64 + r] = v.x;
            sxT[(c4 + 1) * 64 + r] = v.y;
            sxT[(c4 + 2) * 64 + r] = v.z;
            sxT[(c4 + 3) * 64 + r] = v.w;
        }
        if (tid < 192) {
            const int i = tid + 256;
            const int r = i & 63, c4 = (i >> 6) * 4;
            const float4 v = *(const float4*)(xbase + (r >> 3) * H_STR + (r & 7) * 28 + c4);
            sxT[(c4 + 0) * 64 + r] = v.x;
            sxT[(c4 + 1) * 64 + r] = v.y;
            sxT[(c4 + 2) * 64 + r] = v.z;
            sxT[(c4 + 3) * 64 + r] = v.w;
        }
        ((float4*)sWT)[tid] = ((const float4*)g_WT)[tid];
        ((float4*)sWT)[tid + 256] = ((const float4*)g_WT)[tid + 256];
        if (tid < 76)
            ((float4*)sWT)[tid + 512] = ((const float4*)g_WT)[tid + 512];
    }
    __syncthreads();

    // ======== S1: [Q|K|V'] = x @ [W_qk|W_vo]^T ========
    if (tid < 168) {
        const int tgrp = tid / 21, cpos = tid % 21;
        const int t8 = tgrp * 8;
        const float* xb = sxT + t8;
        const float* wb = sWT + 4 * cpos;
        float4 accA[4] = {{0,0,0,0},{0,0,0,0},{0,0,0,0},{0,0,0,0}};
        float4 accB[4] = {{0,0,0,0},{0,0,0,0},{0,0,0,0},{0,0,0,0}};
        #pragma unroll
        for (int k = 0; k < 28; k++) {
            const float4 a0 = *(const float4*)&xb[k * 64];
            const float4 a1 = *(const float4*)&xb[k * 64 + 4];
            const float4 w  = *(const float4*)&wb[k * STW];
            #pragma unroll
            for (int mm = 0; mm < 4; mm++) {
                const float wv = (mm == 0) ? w.x : (mm == 1) ? w.y : (mm == 2) ? w.z : w.w;
                accA[mm].x = fmaf(a0.x, wv, accA[mm].x);
                accA[mm].y = fmaf(a0.y, wv, accA[mm].y);
                accA[mm].z = fmaf(a0.z, wv, accA[mm].z);
                accA[mm].w = fmaf(a0.w, wv, accA[mm].w);
                accB[mm].x = fmaf(a1.x, wv, accB[mm].x);
                accB[mm].y = fmaf(a1.y, wv, accB[mm].y);
                accB[mm].z = fmaf(a1.z, wv, accB[mm].z);
                accB[mm].w = fmaf(a1.w, wv, accB[mm].w);
            }
        }
        #pragma unroll
        for (int mm = 0; mm < 4; mm++) {
            const int c = cpos + 21 * mm;
            if (c < 56) {
                float* dst = (c < 28) ? sqT : skT;
                const int cb = (c < 28) ? c : c - 28;
                const int sw = (cb & 15) << 2;
                *(float4*)&dst[cb * 64 + (t8 ^ sw)]       = accA[mm];
                *(float4*)&dst[cb * 64 + ((t8 + 4) ^ sw)] = accB[mm];
            } else {
                const int d0 = c - 56;
                const float* fa = (const float*)&accA[mm];
                const float* fb = (const float*)&accB[mm];
                #pragma unroll
                for (int tt = 0; tt < 4; tt++) {
                    sv[(t8 + tt) * 28 + d0]     = fa[tt];
                    sv[(t8 + 4 + tt) * 28 + d0] = fb[tt];
                }
            }
        }
    }
    __syncthreads();

    // ======== S2: sigma (tid 128..255) + sim = Q K^T (tid 0..127) ========
    if (tid >= 128) {
        const int id = tid - 128;
        const int i = id & 63;
        const int ri4 = (i >> 2) << 2;
        const int i3  = i & 3;
        if (id < 64) {
            float acc = c_bpcq[0];
            #pragma unroll
            for (int c = 0; c < 28; c++)
                acc = fmaf(sqT[c * 64 + (ri4 ^ ((c & 15) << 2)) + i3], c_Wpcq[c], acc);
            sigq[i] = acc;
        } else {
            float acc = c_bpck[0];
            #pragma unroll
            for (int c = 0; c < 28; c++)
                acc = fmaf(skT[c * 64 + (ri4 ^ ((c & 15) << 2)) + i3], c_Wpck[c], acc);
            sigk[i] = acc;
        }
    } else {
        const int t8 = (tid >> 4) * 8;
        const int j4 = (tid & 15) * 4;
        float4 acc[8] = {{0,0,0,0},{0,0,0,0},{0,0,0,0},{0,0,0,0},
                         {0,0,0,0},{0,0,0,0},{0,0,0,0},{0,0,0,0}};
        #pragma unroll
        for (int k = 0; k < 28; k++) {
            const int sw = (k & 15) << 2;
            const float4 q0 = *(const float4*)&sqT[k * 64 + (t8 ^ sw)];
            const float4 q1 = *(const float4*)&sqT[k * 64 + ((t8 + 4) ^ sw)];
            const float4 kk = *(const float4*)&skT[k * 64 + (j4 ^ sw)];
            #pragma unroll
            for (int tt = 0; tt < 8; tt++) {
                const float qv = (tt == 0) ? q0.x : (tt == 1) ? q0.y : (tt == 2) ? q0.z :
                                 (tt == 3) ? q0.w : (tt == 4) ? q1.x : (tt == 5) ? q1.y :
                                 (tt == 6) ? q1.z : q1.w;
                acc[tt].x = fmaf(qv, kk.x, acc[tt].x);
                acc[tt].y = fmaf(qv, kk.y, acc[tt].y);
                acc[tt].z = fmaf(qv, kk.z, acc[tt].z);
                acc[tt].w = fmaf(qv, kk.w, acc[tt].w);
            }
        }
        float* sb = ssim + t8 * STS + j4;
        #pragma unroll
        for (int tt = 0; tt < 8; tt++)
            *(float4*)&sb[tt * STS] = acc[tt];
    }
    __syncthreads();

    // ======== S3: theta_raw[i] = sum_{j!=i} sim[i,j] * W_m1[j] ========
    if (tid < 64) {
        const float* srow = ssim + tid * STS;
        float acc = 0.f;
        #pragma unroll
        for (int j4 = 0; j4 < 64; j4 += 4) {
            const float4 s = *(const float4*)&srow[j4];
            const float4 w = *(const float4*)&c_Wm1[j4];
            acc = fmaf(s.x, w.x, acc); acc = fmaf(s.y, w.y, acc);
            acc = fmaf(s.z, w.z, acc); acc = fmaf(s.w, w.w, acc);
        }
        acc -= srow[tid] * c_Wm1[tid];
        sth[tid] = acc;
    }
    __syncthreads();

    // ======== S4: theta = W_m2b . LeakyReLU(W_m2a @ theta_raw) ========
    {
        float* scratch = satT;
        const int i = tid & 63, part = tid >> 6;
        const float* col = g_Wm2aT + part * 16 * 64 + i;
        const float* thp = sth + part * 16;
        float acc = 0.f;
        #pragma unroll
        for (int jj = 0; jj < 16; jj++)
            acc = fmaf(col[jj * 64], thp[jj], acc);
        scratch[part * 64 + i] = acc;
        __syncthreads();
        if (tid < 64) {
            float t = scratch[tid] + scratch[64 + tid] + scratch[128 + tid] + scratch[192 + tid];
            t = (t >= 0.f) ? t : 0.1f * t;
            float val = t * c_Wm2b[tid];
            #pragma unroll
            for (int o = 16; o > 0; o >>= 1)
                val += __shfl_down_sync(0xffffffffu, val, o);
            if ((tid & 31) == 0) sred[tid >> 5] = val;
        }
        __syncthreads();
    }
    const float theta = sred[0] + sred[1];

    // ======== S5: softmax, 8 lanes per row, group-of-8 shfl reductions ========
    // thread (rg = tid>>3, sub = tid&7) owns elements j in [sub*8, sub*8+8)
    // of rows rg and rg+32. Store transposed+swizzled for S6.
    {
        const int sub = tid & 7;
        const int rg  = tid >> 3;
        const float4 k0 = *(const float4*)&sigk[sub * 8];
        const float4 k1 = *(const float4*)&sigk[sub * 8 + 4];
        #pragma unroll
        for (int pass = 0; pass < 2; pass++) {
            const int r = rg + pass * 32;
            const float sgq = sigq[r];
            const float4 v0 = *(const float4*)&ssim[r * STS + sub * 8];
            const float4 v1 = *(const float4*)&ssim[r * STS + sub * 8 + 4];
            float s[8];
            s[0] = v0.x * (sgq * k0.x); s[1] = v0.y * (sgq * k0.y);
            s[2] = v0.z * (sgq * k0.z); s[3] = v0.w * (sgq * k0.w);
            s[4] = v1.x * (sgq * k1.x); s[5] = v1.y * (sgq * k1.y);
            s[6] = v1.z * (sgq * k1.z); s[7] = v1.w * (sgq * k1.w);
            float m = fmaxf(fmaxf(fmaxf(s[0], s[1]), fmaxf(s[2], s[3])),
                            fmaxf(fmaxf(s[4], s[5]), fmaxf(s[6], s[7])));
            m = fmaxf(m, __shfl_xor_sync(0xffffffffu, m, 1));
            m = fmaxf(m, __shfl_xor_sync(0xffffffffu, m, 2));
            m = fmaxf(m, __shfl_xor_sync(0xffffffffu, m, 4));
            float e[8];
            #pragma unroll
            for (int u = 0; u < 8; u++) e[u] = __expf(s[u] - m);
            float ss = ((e[0] + e[1]) + (e[2] + e[3])) + ((e[4] + e[5]) + (e[6] + e[7]));
            ss += __shfl_xor_sync(0xffffffffu, ss, 1);
            ss += __shfl_xor_sync(0xffffffffu, ss, 2);
            ss += __shfl_xor_sync(0xffffffffu, ss, 4);
            const float inv = 1.0f / ss;
            // element (j = sub*8+jj, token r) -> j*STS + ((r&~7)^(sub<<3)) + (r&7)
            float* sbase = satT + (sub * 8) * STS + ((r & ~7) ^ (sub << 3)) + (r & 7);
            #pragma unroll
            for (int jj = 0; jj < 8; jj++)
                sbase[jj * STS] = (s[jj] > theta) ? e[jj] * inv : 0.f;
        }
    }
    __syncthreads();

    // ======== S6: out = attn @ V' + b_out. 56 threads, 8t x 4d tiles ========
    if (tid < 56) {
        const int tgrp = tid / 7, dpos = tid % 7;
        const int t8 = tgrp * 8, d4 = dpos * 4;
        const float* vb = sv + d4;
        float4 acc[8] = {{0,0,0,0},{0,0,0,0},{0,0,0,0},{0,0,0,0},
                         {0,0,0,0},{0,0,0,0},{0,0,0,0},{0,0,0,0}};
        #pragma unroll
        for (int j = 0; j < 64; j++) {
            const int base = j * STS + (t8 ^ ((j >> 3) << 3));
            const float4 at0 = *(const float4*)&satT[base];
            const float4 at1 = *(const float4*)&satT[base + 4];
            const float4 vv  = *(const float4*)&vb[j * 28];
            #pragma unroll
            for (int tt = 0; tt < 8; tt++) {
                const float av = (tt == 0) ? at0.x : (tt == 1) ? at0.y : (tt == 2) ? at0.z :
                                 (tt == 3) ? at0.w : (tt == 4) ? at1.x : (tt == 5) ? at1.y :
                                 (tt == 6) ? at1.z : at1.w;
                acc[tt].x = fmaf(av, vv.x, acc[tt].x);
                acc[tt].y = fmaf(av, vv.y, acc[tt].y);
                acc[tt].z = fmaf(av, vv.z, acc[tt].z);
                acc[tt].w = fmaf(av, vv.w, acc[tt].w);
            }
        }
        const float4 bb = *(const float4*)&c_bout[d4];
        #pragma unroll
        for (int tt = 0; tt < 8; tt++) {
            const int t = t8 + tt;
            float* ob = out + (size_t)Bi * B_STR + (wh * 8 + (t >> 3)) * H_STR
                        + (ww * 8 + (t & 7)) * 28 + d4;
            *(float4*)ob = make_float4(acc[tt].x + bb.x, acc[tt].y + bb.y,
                                       acc[tt].z + bb.z, acc[tt].w + bb.w);
        }
    }
}

extern "C" void kernel_launch(void* const* d_in, const int* in_sizes, int n_in,
                              void* d_out, int out_size) {
    (void)in_sizes; (void)n_in; (void)out_size;
    cudaFuncSetAttribute(ipb_kernel, cudaFuncAttributeMaxDynamicSharedMemorySize, SM_BYTES);
    cudaMemcpyToSymbolAsync(c_bout,  d_in[4],  28 * 4, 0, cudaMemcpyDeviceToDevice, 0);
    cudaMemcpyToSymbolAsync(c_Wpcq,  d_in[5],  28 * 4, 0, cudaMemcpyDeviceToDevice, 0);
    cudaMemcpyToSymbolAsync(c_bpcq,  d_in[6],   1 * 4, 0, cudaMemcpyDeviceToDevice, 0);
    cudaMemcpyToSymbolAsync(c_Wpck,  d_in[7],  28 * 4, 0, cudaMemcpyDeviceToDevice, 0);
    cudaMemcpyToSymbolAsync(c_bpck,  d_in[8],   1 * 4, 0, cudaMemcpyDeviceToDevice, 0);
    cudaMemcpyToSymbolAsync(c_Wm1,   d_in[9],  64 * 4, 0, cudaMemcpyDeviceToDevice, 0);
    cudaMemcpyToSymbolAsync(c_Wm2b,  d_in[11], 64 * 4, 0, cudaMemcpyDeviceToDevice, 0);
    prep_kernel<<<16, TPB>>>(
        (const float*)d_in[1],   // W_qk
        (const float*)d_in[2],   // W_v
        (const float*)d_in[3],   // W_out
        (const float*)d_in[10]); // W_m2a
    ipb_kernel<<<8192, TPB, SM_BYTES>>>(
        (const float*)d_in[0],   // x
        (float*)d_out);
}

// round 10
// speedup vs baseline: 1.0896x; 1.0896x over previous
#include <cuda_runtime.h>

// ---------------------------------------------------------------------------
// IPB windowed inhibition attention, fp32. Round 10:
//  - 5 CTAs/SM: smem compacted to 40.9KB (swizzled stride-64 ssim/satT
//    aliased over dead regions), all stages <=4x4 tiles to fit 51 regs
//  - divergent small-weight reads via LDG (g_small); uniform via __constant__
//  - single memcpyToSymbol (prep packs g_small)
// One CTA per (window, B): 8192 CTAs x 256 threads.
// ---------------------------------------------------------------------------

#define TPB 256

namespace {
constexpr int H_STR = 256 * 28;
constexpr int B_STR = 256 * 256 * 28;
constexpr int STW = 84;

// phase-1 layout
constexpr int OFF_XT = 0;       // [28][64] x^T
constexpr int OFF_WT = 1792;    // [28][84] permuted W^T      (ends 4144)
constexpr int OFF_V  = 4144;    // [64][28] V'                (ends 5936)
constexpr int OFF_QT = 5936;    // [28][64] swizzled          (ends 7728)
constexpr int OFF_KT = 7728;    // [28][64] swizzled          (ends 9520)
// phase-2 aliases
constexpr int OFF_SIM = 0;      // [64][64] swizzled (over xT+WT, 4096<=4144)
constexpr int OFF_AT  = 5936;   // [64][64] swizzled (over qT/kT + 512 fresh)
// persistent small
constexpr int OFF_SGQ = 10032;
constexpr int OFF_SGK = 10096;
constexpr int OFF_TH  = 10160;
constexpr int OFF_RED = 10224;
constexpr int SM_FLOATS = 10228;
constexpr int SM_BYTES  = SM_FLOATS * 4;   // 40912 B -> 5 CTAs/SM @ 51 regs

// g_small layout (floats)
constexpr int GS_BOUT = 0;     // 28
constexpr int GS_WM1  = 32;    // 64
constexpr int GS_WM2B = 96;    // 64
constexpr int GS_WPCQ = 160;   // 28
constexpr int GS_WPCK = 192;   // 28
constexpr int GS_BPCQ = 224;
constexpr int GS_BPCK = 225;
constexpr int GS_TOTAL = 240;
}

// prepared weights
__device__ __align__(16) float g_WT[28 * 84];      // [k][c'] permuted W_qk^T|W_vo^T
__device__ __align__(16) float g_Wm2aT[64 * 64];   // [j][i]
__device__ __align__(16) float g_small[GS_TOTAL];  // packed small vectors

// uniform-access copy of g_small in constant bank
__constant__ __align__(16) float c_small[GS_TOTAL];

__global__ void __launch_bounds__(TPB) prep_kernel(
    const float* __restrict__ W_qk,   // [56,28]
    const float* __restrict__ W_v,    // [28,28]
    const float* __restrict__ W_out,  // [28,28]
    const float* __restrict__ W_m2a,  // [64,64]
    const float* __restrict__ b_out,  // [28]
    const float* __restrict__ W_pcq,  // [28]
    const float* __restrict__ b_pcq,  // [1]
    const float* __restrict__ W_pck,  // [28]
    const float* __restrict__ b_pck,  // [1]
    const float* __restrict__ W_m1,   // [64]
    const float* __restrict__ W_m2b)  // [64]
{
    const int gtid = blockIdx.x * TPB + threadIdx.x;
    const int gstep = gridDim.x * TPB;
    for (int i = gtid; i < 1568; i += gstep) {
        const int c = i % 56, k = i / 56;
        const int cp = 4 * (c % 21) + (c / 21);
        g_WT[k * STW + cp] = W_qk[c * 28 + k];
    }
    for (int i = gtid; i < 784; i += gstep) {
        const int c = i / 28, e = i % 28;
        float acc = 0.f;
        #pragma unroll 7
        for (int d = 0; d < 28; d++)
            acc = fmaf(W_out[c * 28 + d], W_v[d * 28 + e], acc);
        const int lc = 56 + c;
        const int cp = 4 * (lc % 21) + (lc / 21);
        g_WT[e * STW + cp] = acc;
    }
    for (int i = gtid; i < 4096; i += gstep) {
        const int r = i >> 6, cc = i & 63;
        g_Wm2aT[cc * 64 + r] = W_m2a[i];
    }
    // pack small vectors
    if (blockIdx.x == 0) {
        const int t = threadIdx.x;
        if (t < 28) g_small[GS_BOUT + t] = b_out[t];
        else if (t < 92)  g_small[GS_WM1  + t - 28] = W_m1[t - 28];
        else if (t < 156) g_small[GS_WM2B + t - 92] = W_m2b[t - 92];
        else if (t < 184) g_small[GS_WPCQ + t - 156] = W_pcq[t - 156];
        else if (t < 212) g_small[GS_WPCK + t - 184] = W_pck[t - 184];
        else if (t == 212) g_small[GS_BPCQ] = b_pcq[0];
        else if (t == 213) g_small[GS_BPCK] = b_pck[0];
    }
}

__global__ void __launch_bounds__(TPB, 5) ipb_kernel(
    const float* __restrict__ x,
    float* __restrict__ out)
{
    extern __shared__ float sm[];
    float* sxT  = sm + OFF_XT;
    float* sWT  = sm + OFF_WT;
    float* sv   = sm + OFF_V;
    float* sqT  = sm + OFF_QT;
    float* skT  = sm + OFF_KT;
    float* ssim = sm + OFF_SIM;
    float* satT = sm + OFF_AT;
    float* sigq = sm + OFF_SGQ;
    float* sigk = sm + OFF_SGK;
    float* sth  = sm + OFF_TH;
    float* sred = sm + OFF_RED;

    const int tid  = threadIdx.x;
    const int widx = blockIdx.x & 1023;
    const int Bi   = blockIdx.x >> 10;
    const int wh = widx >> 5, ww = widx & 31;
    const float* xbase = x + (size_t)Bi * B_STR + wh * 8 * H_STR + ww * 8 * 28;

    // ======== S0: x transpose + weight copy ========
    {
        {
            const int r = tid & 63, c4 = (tid >> 6) * 4;
            const float4 v = *(const float4*)(xbase + (r >> 3) * H_STR + (r & 7) * 28 + c4);
            sxT[(c4 + 0) * 64 + r] = v.x;
            sxT[(c4 + 1) * 64 + r] = v.y;
            sxT[(c4 + 2) * 64 + r] = v.z;
            sxT[(c4 + 3) * 64 + r] = v.w;
        }
        if (tid < 192) {
            const int i = tid + 256;
            const int r = i & 63, c4 = (i >> 6) * 4;
            const float4 v = *(const float4*)(xbase + (r >> 3) * H_STR + (r & 7) * 28 + c4);
            sxT[(c4 + 0) * 64 + r] = v.x;
            sxT[(c4 + 1) * 64 + r] = v.y;
            sxT[(c4 + 2) * 64 + r] = v.z;
            sxT[(c4 + 3) * 64 + r] = v.w;
        }
        ((float4*)sWT)[tid] = ((const float4*)g_WT)[tid];
        ((float4*)sWT)[tid + 256] = ((const float4*)g_WT)[tid + 256];
        if (tid < 76)
            ((float4*)sWT)[tid + 512] = ((const float4*)g_WT)[tid + 512];
    }
    __syncthreads();

    // ======== S1: [Q|K|V'] = x @ [W_qk|W_vo]^T, 4-token x 4-col units ========
    #pragma unroll
    for (int u = tid; u < 336; u += TPB) {
        const int t4 = (u / 21) * 4, cpos = u % 21;
        const float* xb = sxT + t4;
        const float* wb = sWT + 4 * cpos;
        float4 acc[4] = {{0,0,0,0},{0,0,0,0},{0,0,0,0},{0,0,0,0}};
        #pragma unroll
        for (int k = 0; k < 28; k++) {
            const float4 a = *(const float4*)&xb[k * 64];
            const float4 w = *(const float4*)&wb[k * STW];
            #pragma unroll
            for (int mm = 0; mm < 4; mm++) {
                const float wv = (mm == 0) ? w.x : (mm == 1) ? w.y : (mm == 2) ? w.z : w.w;
                acc[mm].x = fmaf(a.x, wv, acc[mm].x);
                acc[mm].y = fmaf(a.y, wv, acc[mm].y);
                acc[mm].z = fmaf(a.z, wv, acc[mm].z);
                acc[mm].w = fmaf(a.w, wv, acc[mm].w);
            }
        }
        const int tq = t4 >> 2;   // 0..15
        #pragma unroll
        for (int mm = 0; mm < 4; mm++) {
            const int c = cpos + 21 * mm;
            if (c < 56) {
                float* dst = (c < 28) ? sqT : skT;
                const int cb = (c < 28) ? c : c - 28;
                *(float4*)&dst[cb * 64 + 4 * ((tq ^ cb) & 15)] = acc[mm];
            } else {
                const int d0 = c - 56;
                const float* fa = (const float*)&acc[mm];
                #pragma unroll
                for (int tt = 0; tt < 4; tt++)
                    sv[(t4 + tt) * 28 + d0] = fa[tt];
            }
        }
    }
    __syncthreads();

    // ======== S2: sim = Q K^T (all 256, 4x4) then sigma (128) ========
    {
        const int t4 = (tid >> 4) * 4;
        const int j4 = (tid & 15) * 4;
        const int tq = t4 >> 2, jq = j4 >> 2;
        float4 acc[4] = {{0,0,0,0},{0,0,0,0},{0,0,0,0},{0,0,0,0}};
        #pragma unroll
        for (int k = 0; k < 28; k++) {
            const float4 q = *(const float4*)&sqT[k * 64 + 4 * ((tq ^ k) & 15)];
            const float4 kk = *(const float4*)&skT[k * 64 + 4 * ((jq ^ k) & 15)];
            #pragma unroll
            for (int tt = 0; tt < 4; tt++) {
                const float qv = (tt == 0) ? q.x : (tt == 1) ? q.y : (tt == 2) ? q.z : q.w;
                acc[tt].x = fmaf(qv, kk.x, acc[tt].x);
                acc[tt].y = fmaf(qv, kk.y, acc[tt].y);
                acc[tt].z = fmaf(qv, kk.z, acc[tt].z);
                acc[tt].w = fmaf(qv, kk.w, acc[tt].w);
            }
        }
        // ssim[r][j] at r*64 + 4*((jq ^ (r&15)) & 15) + (j&3)
        #pragma unroll
        for (int tt = 0; tt < 4; tt++) {
            const int r = t4 + tt;
            *(float4*)&ssim[r * 64 + 4 * ((jq ^ (r & 15)) & 15)] = acc[tt];
        }
    }
    if (tid < 128) {
        const int i = tid & 63;
        const int iq = i >> 2, i3 = i & 3;
        if (tid < 64) {
            float acc = c_small[GS_BPCQ];
            #pragma unroll
            for (int c = 0; c < 28; c++)
                acc = fmaf(sqT[c * 64 + 4 * ((iq ^ c) & 15) + i3], c_small[GS_WPCQ + c], acc);
            sigq[i] = acc;
        } else {
            float acc = c_small[GS_BPCK];
            #pragma unroll
            for (int c = 0; c < 28; c++)
                acc = fmaf(skT[c * 64 + 4 * ((iq ^ c) & 15) + i3], c_small[GS_WPCK + c], acc);
            sigk[i] = acc;
        }
    }
    __syncthreads();

    // ======== S3: theta_raw[i] = sum_{j!=i} sim[i,j] * W_m1[j] ========
    if (tid < 64) {
        const int r = tid, rx = r & 15;
        const float* srow = ssim + r * 64;
        float acc = 0.f;
        #pragma unroll
        for (int j4 = 0; j4 < 64; j4 += 4) {
            const float4 s = *(const float4*)&srow[4 * (((j4 >> 2) ^ rx) & 15)];
            const float4 w = *(const float4*)&c_small[GS_WM1 + j4];
            acc = fmaf(s.x, w.x, acc); acc = fmaf(s.y, w.y, acc);
            acc = fmaf(s.z, w.z, acc); acc = fmaf(s.w, w.w, acc);
        }
        const float diag = srow[4 * (((r >> 2) ^ rx) & 15) + (r & 3)];
        acc -= diag * g_small[GS_WM1 + r];   // divergent -> LDG
        sth[r] = acc;
    }
    __syncthreads();

    // ======== S4: theta = W_m2b . LeakyReLU(W_m2a @ theta_raw) ========
    {
        float* scratch = satT;   // qT/kT region, dead after S2
        const int i = tid & 63, part = tid >> 6;
        const float* col = g_Wm2aT + part * 16 * 64 + i;
        const float* thp = sth + part * 16;
        float acc = 0.f;
        #pragma unroll
        for (int jj = 0; jj < 16; jj++)
            acc = fmaf(col[jj * 64], thp[jj], acc);
        scratch[part * 64 + i] = acc;
        __syncthreads();
        if (tid < 64) {
            float t = scratch[tid] + scratch[64 + tid] + scratch[128 + tid] + scratch[192 + tid];
            t = (t >= 0.f) ? t : 0.1f * t;
            float val = t * g_small[GS_WM2B + tid];   // divergent -> LDG
            #pragma unroll
            for (int o = 16; o > 0; o >>= 1)
                val += __shfl_down_sync(0xffffffffu, val, o);
            if ((tid & 31) == 0) sred[tid >> 5] = val;
        }
        __syncthreads();
    }
    const float theta = sred[0] + sred[1];

    // ======== S5: softmax, 8 lanes/row; write attn transposed+swizzled ========
    {
        const int sub = tid & 7;
        const int rg  = tid >> 3;
        const float4 k0 = *(const float4*)&sigk[sub * 8];
        const float4 k1 = *(const float4*)&sigk[sub * 8 + 4];
        #pragma unroll
        for (int pass = 0; pass < 2; pass++) {
            const int r = rg + pass * 32;
            const int rx = r & 15;
            const float sgq = sigq[r];
            const float4 v0 = *(const float4*)&ssim[r * 64 + 4 * (((sub * 2) ^ rx) & 15)];
            const float4 v1 = *(const float4*)&ssim[r * 64 + 4 * (((sub * 2 + 1) ^ rx) & 15)];
            float s[8];
            s[0] = v0.x * (sgq * k0.x); s[1] = v0.y * (sgq * k0.y);
            s[2] = v0.z * (sgq * k0.z); s[3] = v0.w * (sgq * k0.w);
            s[4] = v1.x * (sgq * k1.x); s[5] = v1.y * (sgq * k1.y);
            s[6] = v1.z * (sgq * k1.z); s[7] = v1.w * (sgq * k1.w);
            float m = fmaxf(fmaxf(fmaxf(s[0], s[1]), fmaxf(s[2], s[3])),
                            fmaxf(fmaxf(s[4], s[5]), fmaxf(s[6], s[7])));
            m = fmaxf(m, __shfl_xor_sync(0xffffffffu, m, 1));
            m = fmaxf(m, __shfl_xor_sync(0xffffffffu, m, 2));
            m = fmaxf(m, __shfl_xor_sync(0xffffffffu, m, 4));
            float e[8];
            #pragma unroll
            for (int u = 0; u < 8; u++) e[u] = __expf(s[u] - m);
            float ss = ((e[0] + e[1]) + (e[2] + e[3])) + ((e[4] + e[5]) + (e[6] + e[7]));
            ss += __shfl_xor_sync(0xffffffffu, ss, 1);
            ss += __shfl_xor_sync(0xffffffffu, ss, 2);
            ss += __shfl_xor_sync(0xffffffffu, ss, 4);
            const float inv = 1.0f / ss;
            // satT[j][t] at j*64 + ((t&~7) ^ ((j>>3)<<3)) + (t&7); j = sub*8+jj
            float* sbase = satT + (sub * 8) * 64 + ((r & ~7) ^ (sub << 3)) + (r & 7);
            #pragma unroll
            for (int jj = 0; jj < 8; jj++)
                sbase[jj * 64] = (s[jj] > theta) ? e[jj] * inv : 0.f;
        }
    }
    __syncthreads();

    // ======== S6: out = attn @ V' + b_out. 112 threads, 4t x 4d ========
    if (tid < 112) {
        const int tgrp = tid / 7, dpos = tid % 7;
        const int t4 = tgrp * 4, d4 = dpos * 4;
        const int thi = t4 & ~7, tlo = t4 & 7;
        const float* vb = sv + d4;
        float4 acc[4] = {{0,0,0,0},{0,0,0,0},{0,0,0,0},{0,0,0,0}};
        #pragma unroll
        for (int j = 0; j < 64; j++) {
            const float4 at = *(const float4*)&satT[j * 64 + (thi ^ ((j >> 3) << 3)) + tlo];
            const float4 vv = *(const float4*)&vb[j * 28];
            #pragma unroll
            for (int tt = 0; tt < 4; tt++) {
                const float av = (tt == 0) ? at.x : (tt == 1) ? at.y : (tt == 2) ? at.z : at.w;
                acc[tt].x = fmaf(av, vv.x, acc[tt].x);
                acc[tt].y = fmaf(av, vv.y, acc[tt].y);
                acc[tt].z = fmaf(av, vv.z, acc[tt].z);
                acc[tt].w = fmaf(av, vv.w, acc[tt].w);
            }
        }
        const float4 bb = *(const float4*)&g_small[GS_BOUT + d4];   // LDG
        #pragma unroll
        for (int tt = 0; tt < 4; tt++) {
            const int t = t4 + tt;
            float* ob = out + (size_t)Bi * B_STR + (wh * 8 + (t >> 3)) * H_STR
                        + (ww * 8 + (t & 7)) * 28 + d4;
            *(float4*)ob = make_float4(acc[tt].x + bb.x, acc[tt].y + bb.y,
                                       acc[tt].z + bb.z, acc[tt].w + bb.w);
        }
    }
}

extern "C" void kernel_launch(void* const* d_in, const int* in_sizes, int n_in,
                              void* d_out, int out_size) {
    (void)in_sizes; (void)n_in; (void)out_size;
    cudaFuncSetAttribute(ipb_kernel, cudaFuncAttributeMaxDynamicSharedMemorySize, SM_BYTES);
    prep_kernel<<<16, TPB>>>(
        (const float*)d_in[1],   // W_qk
        (const float*)d_in[2],   // W_v
        (const float*)d_in[3],   // W_out
        (const float*)d_in[10],  // W_m2a
        (const float*)d_in[4],   // b_out
        (const float*)d_in[5],   // W_pcq
        (const float*)d_in[6],   // b_pcq
        (const float*)d_in[7],   // W_pck
        (const float*)d_in[8],   // b_pck
        (const float*)d_in[9],   // W_m1
        (const float*)d_in[11]); // W_m2b
    // single constant-bank refresh from the packed device array
    void* gsp = nullptr;
    cudaGetSymbolAddress(&gsp, g_small);
    cudaMemcpyToSymbolAsync(c_small, gsp, GS_TOTAL * 4, 0, cudaMemcpyDeviceToDevice, 0);
    ipb_kernel<<<8192, TPB, SM_BYTES>>>(
        (const float*)d_in[0],   // x
        (float*)d_out);
}

// round 11
// speedup vs baseline: 1.1676x; 1.0716x over previous
#include <cuda_runtime.h>

// ---------------------------------------------------------------------------
// IPB windowed inhibition attention, fp32. Round 11:
//  - S1 lane remap: QK/sigma block t-fast (broadcast W loads), V block
//    cpos-fast (conflict-free V stores)
//  - sigma folded into S1 as extra W columns (prep computes W^T w_pc)
//  - 5 CTAs/SM (41.4KB smem, 48-reg cap); swizzled stride-64 sim/attn
// One CTA per (window, B): 8192 CTAs x 256 threads.
// ---------------------------------------------------------------------------

#define TPB 256

namespace {
constexpr int H_STR = 256 * 28;
constexpr int B_STR = 256 * 256 * 28;
constexpr int STW = 88;     // sWT [28][88]

// phase-1 layout
constexpr int OFF_XT = 0;       // [28][64] x^T
constexpr int OFF_WT = 1792;    // [28][88] permuted W^T      (ends 4256)
constexpr int OFF_V  = 4256;    // [64][28] V'                (ends 6048)
constexpr int OFF_QT = 6048;    // [28][64] swizzled          (ends 7840)
constexpr int OFF_KT = 7840;    // [28][64] swizzled          (ends 9632)
// phase-2 aliases
constexpr int OFF_SIM = 0;      // [64][64] swizzled (over xT+WT head, 4096<=4256)
constexpr int OFF_AT  = 6048;   // [64][64] swizzled (over qT/kT + 512 fresh)
// persistent small
constexpr int OFF_SGQ = 10144;
constexpr int OFF_SGK = 10208;
constexpr int OFF_TH  = 10272;
constexpr int OFF_RED = 10336;
constexpr int SM_FLOATS = 10340;
constexpr int SM_BYTES  = SM_FLOATS * 4;   // 41360 B -> 5 CTAs/SM

// g_small layout (floats)
constexpr int GS_BOUT = 0;     // 28
constexpr int GS_WM1  = 32;    // 64
constexpr int GS_WM2B = 96;    // 64
constexpr int GS_BPCQ = 160;
constexpr int GS_BPCK = 161;
constexpr int GS_TOTAL = 176;

// W column blocks:
//  block1 (60 logical cols, cpos 0..14): c1 = cpos + 15*mm
//    c1: 0..27 Q | 28..55 K | 56 sigma_q | 57 sigma_k | 58,59 zero-pad
//    permuted position: cp = 4*(c1 % 15) + c1/15
//  block2 (28 V cols, cpos2 0..6): c2 = cpos2 + 7*mm
//    permuted position: cp = 60 + 4*(c2 % 7) + c2/7
}

__device__ __align__(16) float g_WT[28 * STW];
__device__ __align__(16) float g_Wm2aT[64 * 64];   // [j][i]
__device__ __align__(16) float g_small[GS_TOTAL];
__constant__ __align__(16) float c_small[GS_TOTAL];

__global__ void __launch_bounds__(TPB) prep_kernel(
    const float* __restrict__ W_qk,   // [56,28]
    const float* __restrict__ W_v,    // [28,28]
    const float* __restrict__ W_out,  // [28,28]
    const float* __restrict__ W_m2a,  // [64,64]
    const float* __restrict__ b_out,  // [28]
    const float* __restrict__ W_pcq,  // [28]
    const float* __restrict__ b_pcq,  // [1]
    const float* __restrict__ W_pck,  // [28]
    const float* __restrict__ b_pck,  // [1]
    const float* __restrict__ W_m1,   // [64]
    const float* __restrict__ W_m2b)  // [64]
{
    const int gtid = blockIdx.x * TPB + threadIdx.x;
    const int gstep = gridDim.x * TPB;
    // Q/K columns (block1)
    for (int i = gtid; i < 1568; i += gstep) {
        const int c = i % 56, k = i / 56;
        const int cp = 4 * (c % 15) + (c / 15);
        g_WT[k * STW + cp] = W_qk[c * 28 + k];
    }
    // V' = W_out @ W_v columns (block2)
    for (int i = gtid; i < 784; i += gstep) {
        const int c = i / 28, e = i % 28;
        float acc = 0.f;
        #pragma unroll 7
        for (int d = 0; d < 28; d++)
            acc = fmaf(W_out[c * 28 + d], W_v[d * 28 + e], acc);
        g_WT[e * STW + 60 + 4 * (c % 7) + (c / 7)] = acc;
    }
    // sigma columns (wx = W^T w_pc) + zero pads
    for (int i = gtid; i < 112; i += gstep) {
        const int e = i % 28, which = i / 28;
        if (which < 2) {
            const float* wp = (which == 0) ? W_pcq : W_pck;
            const int coff = (which == 0) ? 0 : 28;
            float acc = 0.f;
            #pragma unroll 7
            for (int c = 0; c < 28; c++)
                acc = fmaf(wp[c], W_qk[(coff + c) * 28 + e], acc);
            g_WT[e * STW + ((which == 0) ? 47 : 51)] = acc;  // cp(56)=47, cp(57)=51
        } else {
            g_WT[e * STW + ((which == 2) ? 55 : 59)] = 0.f;  // cp(58)=55, cp(59)=59
        }
    }
    // W_m2a^T
    for (int i = gtid; i < 4096; i += gstep) {
        const int r = i >> 6, cc = i & 63;
        g_Wm2aT[cc * 64 + r] = W_m2a[i];
    }
    // pack small vectors
    if (blockIdx.x == 0) {
        const int t = threadIdx.x;
        if (t < 28) g_small[GS_BOUT + t] = b_out[t];
        else if (t < 92)  g_small[GS_WM1  + t - 28] = W_m1[t - 28];
        else if (t < 156) g_small[GS_WM2B + t - 92] = W_m2b[t - 92];
        else if (t == 156) g_small[GS_BPCQ] = b_pcq[0];
        else if (t == 157) g_small[GS_BPCK] = b_pck[0];
    }
}

__global__ void __launch_bounds__(TPB, 5) ipb_kernel(
    const float* __restrict__ x,
    float* __restrict__ out)
{
    extern __shared__ float sm[];
    float* sxT  = sm + OFF_XT;
    float* sWT  = sm + OFF_WT;
    float* sv   = sm + OFF_V;
    float* sqT  = sm + OFF_QT;
    float* skT  = sm + OFF_KT;
    float* ssim = sm + OFF_SIM;
    float* satT = sm + OFF_AT;
    float* sigq = sm + OFF_SGQ;
    float* sigk = sm + OFF_SGK;
    float* sth  = sm + OFF_TH;
    float* sred = sm + OFF_RED;

    const int tid  = threadIdx.x;
    const int widx = blockIdx.x & 1023;
    const int Bi   = blockIdx.x >> 10;
    const int wh = widx >> 5, ww = widx & 31;
    const float* xbase = x + (size_t)Bi * B_STR + wh * 8 * H_STR + ww * 8 * 28;

    // ======== S0: x transpose + weight copy ========
    {
        {
            const int r = tid & 63, c4 = (tid >> 6) * 4;
            const float4 v = *(const float4*)(xbase + (r >> 3) * H_STR + (r & 7) * 28 + c4);
            sxT[(c4 + 0) * 64 + r] = v.x;
            sxT[(c4 + 1) * 64 + r] = v.y;
            sxT[(c4 + 2) * 64 + r] = v.z;
            sxT[(c4 + 3) * 64 + r] = v.w;
        }
        if (tid < 192) {
            const int i = tid + 256;
            const int r = i & 63, c4 = (i >> 6) * 4;
            const float4 v = *(const float4*)(xbase + (r >> 3) * H_STR + (r & 7) * 28 + c4);
            sxT[(c4 + 0) * 64 + r] = v.x;
            sxT[(c4 + 1) * 64 + r] = v.y;
            sxT[(c4 + 2) * 64 + r] = v.z;
            sxT[(c4 + 3) * 64 + r] = v.w;
        }
        ((float4*)sWT)[tid]       = ((const float4*)g_WT)[tid];
        ((float4*)sWT)[tid + 256] = ((const float4*)g_WT)[tid + 256];
        if (tid < 104)
            ((float4*)sWT)[tid + 512] = ((const float4*)g_WT)[tid + 512];
    }
    __syncthreads();

    // ======== S1: [Q|K|sigma|V'] = x @ W^T ========
    // unit u: u<240 -> block1 (t-fast: t16=u&15, cpos=u>>4) ; u>=240 -> block2 (V)
    auto s1_unit = [&](int u) {
        if (u < 240) {
            const int t16 = u & 15, cpos = u >> 4;
            const int t4 = t16 * 4;
            const float* xb = sxT + t4;
            const float* wb = sWT + 4 * cpos;
            float4 acc[4] = {{0,0,0,0},{0,0,0,0},{0,0,0,0},{0,0,0,0}};
            #pragma unroll
            for (int k = 0; k < 28; k++) {
                const float4 a = *(const float4*)&xb[k * 64];
                const float4 w = *(const float4*)&wb[k * STW];
                #pragma unroll
                for (int mm = 0; mm < 4; mm++) {
                    const float wv = (mm == 0) ? w.x : (mm == 1) ? w.y : (mm == 2) ? w.z : w.w;
                    acc[mm].x = fmaf(a.x, wv, acc[mm].x);
                    acc[mm].y = fmaf(a.y, wv, acc[mm].y);
                    acc[mm].z = fmaf(a.z, wv, acc[mm].z);
                    acc[mm].w = fmaf(a.w, wv, acc[mm].w);
                }
            }
            #pragma unroll
            for (int mm = 0; mm < 4; mm++) {
                const int c = cpos + 15 * mm;
                const float* fa = (const float*)&acc[mm];
                if (c < 56) {
                    float* dst = (c < 28) ? sqT : skT;
                    const int cb = (c < 28) ? c : c - 28;
                    *(float4*)&dst[cb * 64 + 4 * ((t16 ^ cb) & 15)] = acc[mm];
                } else if (c == 56) {
                    const float bq = c_small[GS_BPCQ];
                    #pragma unroll
                    for (int tt = 0; tt < 4; tt++) sigq[t4 + tt] = fa[tt] + bq;
                } else if (c == 57) {
                    const float bk = c_small[GS_BPCK];
                    #pragma unroll
                    for (int tt = 0; tt < 4; tt++) sigk[t4 + tt] = fa[tt] + bk;
                }
            }
        } else {
            const int v = u - 240;
            const int cpos2 = v % 7, tg = v / 7;
            const int t4 = tg * 4;
            const float* xb = sxT + t4;
            const float* wb = sWT + 60 + 4 * cpos2;
            float4 acc[4] = {{0,0,0,0},{0,0,0,0},{0,0,0,0},{0,0,0,0}};
            #pragma unroll
            for (int k = 0; k < 28; k++) {
                const float4 a = *(const float4*)&xb[k * 64];
                const float4 w = *(const float4*)&wb[k * STW];
                #pragma unroll
                for (int mm = 0; mm < 4; mm++) {
                    const float wv = (mm == 0) ? w.x : (mm == 1) ? w.y : (mm == 2) ? w.z : w.w;
                    acc[mm].x = fmaf(a.x, wv, acc[mm].x);
                    acc[mm].y = fmaf(a.y, wv, acc[mm].y);
                    acc[mm].z = fmaf(a.z, wv, acc[mm].z);
                    acc[mm].w = fmaf(a.w, wv, acc[mm].w);
                }
            }
            #pragma unroll
            for (int mm = 0; mm < 4; mm++) {
                const int d0 = cpos2 + 7 * mm;
                const float* fa = (const float*)&acc[mm];
                #pragma unroll
                for (int tt = 0; tt < 4; tt++)
                    sv[(t4 + tt) * 28 + d0] = fa[tt];
            }
        }
    };
    s1_unit(tid);
    if (tid < 96) s1_unit(tid + 256);
    __syncthreads();

    // ======== S2: sim = Q K^T (256 threads, 4x4) ========
    {
        const int t4 = (tid >> 4) * 4;
        const int j4 = (tid & 15) * 4;
        const int tq = t4 >> 2, jq = j4 >> 2;
        float4 acc[4] = {{0,0,0,0},{0,0,0,0},{0,0,0,0},{0,0,0,0}};
        #pragma unroll
        for (int k = 0; k < 28; k++) {
            const float4 q  = *(const float4*)&sqT[k * 64 + 4 * ((tq ^ k) & 15)];
            const float4 kk = *(const float4*)&skT[k * 64 + 4 * ((jq ^ k) & 15)];
            #pragma unroll
            for (int tt = 0; tt < 4; tt++) {
                const float qv = (tt == 0) ? q.x : (tt == 1) ? q.y : (tt == 2) ? q.z : q.w;
                acc[tt].x = fmaf(qv, kk.x, acc[tt].x);
                acc[tt].y = fmaf(qv, kk.y, acc[tt].y);
                acc[tt].z = fmaf(qv, kk.z, acc[tt].z);
                acc[tt].w = fmaf(qv, kk.w, acc[tt].w);
            }
        }
        #pragma unroll
        for (int tt = 0; tt < 4; tt++) {
            const int r = t4 + tt;
            *(float4*)&ssim[r * 64 + 4 * ((jq ^ (r & 15)) & 15)] = acc[tt];
        }
    }
    __syncthreads();

    // ======== S3: theta_raw[i] = sum_{j!=i} sim[i,j] * W_m1[j] ========
    if (tid < 64) {
        const int r = tid, rx = r & 15;
        const float* srow = ssim + r * 64;
        float acc = 0.f;
        #pragma unroll
        for (int j4 = 0; j4 < 64; j4 += 4) {
            const float4 s = *(const float4*)&srow[4 * (((j4 >> 2) ^ rx) & 15)];
            const float4 w = *(const float4*)&c_small[GS_WM1 + j4];
            acc = fmaf(s.x, w.x, acc); acc = fmaf(s.y, w.y, acc);
            acc = fmaf(s.z, w.z, acc); acc = fmaf(s.w, w.w, acc);
        }
        const float diag = srow[4 * (((r >> 2) ^ rx) & 15) + (r & 3)];
        acc -= diag * g_small[GS_WM1 + r];   // divergent -> LDG
        sth[r] = acc;
    }
    __syncthreads();

    // ======== S4: theta = W_m2b . LeakyReLU(W_m2a @ theta_raw) ========
    {
        float* scratch = satT;
        const int i = tid & 63, part = tid >> 6;
        const float* col = g_Wm2aT + part * 16 * 64 + i;
        const float* thp = sth + part * 16;
        float acc = 0.f;
        #pragma unroll
        for (int jj = 0; jj < 16; jj++)
            acc = fmaf(col[jj * 64], thp[jj], acc);
        scratch[part * 64 + i] = acc;
        __syncthreads();
        if (tid < 64) {
            float t = scratch[tid] + scratch[64 + tid] + scratch[128 + tid] + scratch[192 + tid];
            t = (t >= 0.f) ? t : 0.1f * t;
            float val = t * g_small[GS_WM2B + tid];   // divergent -> LDG
            #pragma unroll
            for (int o = 16; o > 0; o >>= 1)
                val += __shfl_down_sync(0xffffffffu, val, o);
            if ((tid & 31) == 0) sred[tid >> 5] = val;
        }
        __syncthreads();
    }
    const float theta = sred[0] + sred[1];

    // ======== S5: softmax, 8 lanes/row; write attn transposed+swizzled ========
    {
        const int sub = tid & 7;
        const int rg  = tid >> 3;
        const float4 k0 = *(const float4*)&sigk[sub * 8];
        const float4 k1 = *(const float4*)&sigk[sub * 8 + 4];
        #pragma unroll
        for (int pass = 0; pass < 2; pass++) {
            const int r = rg + pass * 32;
            const int rx = r & 15;
            const float sgq = sigq[r];
            const float4 v0 = *(const float4*)&ssim[r * 64 + 4 * (((sub * 2) ^ rx) & 15)];
            const float4 v1 = *(const float4*)&ssim[r * 64 + 4 * (((sub * 2 + 1) ^ rx) & 15)];
            float s[8];
            s[0] = v0.x * (sgq * k0.x); s[1] = v0.y * (sgq * k0.y);
            s[2] = v0.z * (sgq * k0.z); s[3] = v0.w * (sgq * k0.w);
            s[4] = v1.x * (sgq * k1.x); s[5] = v1.y * (sgq * k1.y);
            s[6] = v1.z * (sgq * k1.z); s[7] = v1.w * (sgq * k1.w);
            float m = fmaxf(fmaxf(fmaxf(s[0], s[1]), fmaxf(s[2], s[3])),
                            fmaxf(fmaxf(s[4], s[5]), fmaxf(s[6], s[7])));
            m = fmaxf(m, __shfl_xor_sync(0xffffffffu, m, 1));
            m = fmaxf(m, __shfl_xor_sync(0xffffffffu, m, 2));
            m = fmaxf(m, __shfl_xor_sync(0xffffffffu, m, 4));
            float e[8];
            #pragma unroll
            for (int u = 0; u < 8; u++) e[u] = __expf(s[u] - m);
            float ss = ((e[0] + e[1]) + (e[2] + e[3])) + ((e[4] + e[5]) + (e[6] + e[7]));
            ss += __shfl_xor_sync(0xffffffffu, ss, 1);
            ss += __shfl_xor_sync(0xffffffffu, ss, 2);
            ss += __shfl_xor_sync(0xffffffffu, ss, 4);
            const float inv = 1.0f / ss;
            float* sbase = satT + (sub * 8) * 64 + ((r & ~7) ^ (sub << 3)) + (r & 7);
            #pragma unroll
            for (int jj = 0; jj < 8; jj++)
                sbase[jj * 64] = (s[jj] > theta) ? e[jj] * inv : 0.f;
        }
    }
    __syncthreads();

    // ======== S6: out = attn @ V' + b_out. 112 threads, 4t x 4d ========
    if (tid < 112) {
        const int tgrp = tid / 7, dpos = tid % 7;
        const int t4 = tgrp * 4, d4 = dpos * 4;
        const int thi = t4 & ~7, tlo = t4 & 7;
        const float* vb = sv + d4;
        float4 acc[4] = {{0,0,0,0},{0,0,0,0},{0,0,0,0},{0,0,0,0}};
        #pragma unroll
        for (int j = 0; j < 64; j++) {
            const float4 at = *(const float4*)&satT[j * 64 + (thi ^ ((j >> 3) << 3)) + tlo];
            const float4 vv = *(const float4*)&vb[j * 28];
            #pragma unroll
            for (int tt = 0; tt < 4; tt++) {
                const float av = (tt == 0) ? at.x : (tt == 1) ? at.y : (tt == 2) ? at.z : at.w;
                acc[tt].x = fmaf(av, vv.x, acc[tt].x);
                acc[tt].y = fmaf(av, vv.y, acc[tt].y);
                acc[tt].z = fmaf(av, vv.z, acc[tt].z);
                acc[tt].w = fmaf(av, vv.w, acc[tt].w);
            }
        }
        const float4 bb = *(const float4*)&g_small[GS_BOUT + d4];   // LDG
        #pragma unroll
        for (int tt = 0; tt < 4; tt++) {
            const int t = t4 + tt;
            float* ob = out + (size_t)Bi * B_STR + (wh * 8 + (t >> 3)) * H_STR
                        + (ww * 8 + (t & 7)) * 28 + d4;
            *(float4*)ob = make_float4(acc[tt].x + bb.x, acc[tt].y + bb.y,
                                       acc[tt].z + bb.z, acc[tt].w + bb.w);
        }
    }
}

extern "C" void kernel_launch(void* const* d_in, const int* in_sizes, int n_in,
                              void* d_out, int out_size) {
    (void)in_sizes; (void)n_in; (void)out_size;
    cudaFuncSetAttribute(ipb_kernel, cudaFuncAttributeMaxDynamicSharedMemorySize, SM_BYTES);
    prep_kernel<<<16, TPB>>>(
        (const float*)d_in[1],   // W_qk
        (const float*)d_in[2],   // W_v
        (const float*)d_in[3],   // W_out
        (const float*)d_in[10],  // W_m2a
        (const float*)d_in[4],   // b_out
        (const float*)d_in[5],   // W_pcq
        (const float*)d_in[6],   // b_pcq
        (const float*)d_in[7],   // W_pck
        (const float*)d_in[8],   // b_pck
        (const float*)d_in[9],   // W_m1
        (const float*)d_in[11]); // W_m2b
    void* gsp = nullptr;
    cudaGetSymbolAddress(&gsp, g_small);
    cudaMemcpyToSymbolAsync(c_small, gsp, GS_TOTAL * 4, 0, cudaMemcpyDeviceToDevice, 0);
    ipb_kernel<<<8192, TPB, SM_BYTES>>>(
        (const float*)d_in[0],   // x
        (float*)d_out);
}

// round 12
// speedup vs baseline: 1.3309x; 1.1398x over previous
#include <cuda_runtime.h>

// ---------------------------------------------------------------------------
// IPB windowed inhibition attention, fp32. Round 12:
//  - Q/K eliminated: sim = x (W_q^T W_k) x^T; prep computes M = W_q^T W_k.
//    S1 outputs only y = x M, V' = x (W_out W_v)^T, sigma (folded cols).
//  - attn buffer swizzle reworked -> S5 stores conflict-free
//  - 5 CTAs/SM (45.4KB smem, 48-reg cap)
// One CTA per (window, B): 8192 CTAs x 256 threads.
// ---------------------------------------------------------------------------

#define TPB 256

namespace {
constexpr int H_STR = 256 * 28;
constexpr int B_STR = 256 * 256 * 28;
constexpr int STW = 60;     // sWT [28][60]

// layout (floats)
constexpr int OFF_XT  = 0;       // [28][64] x^T (plain)
constexpr int OFF_YT  = 1792;    // [28][64] y^T (swizzled)
constexpr int OFF_WT  = 3584;    // [28][60] permuted weights   (ends 5264)
constexpr int OFF_V   = 5264;    // [64][28] V'                 (ends 7056)
constexpr int OFF_SIM = 7056;    // [64][64] swizzled           (ends 11152)
constexpr int OFF_AT  = 0;       // attnT [64][64] alias (xT/yT/WT-head dead after S2)
constexpr int OFF_SGQ = 11152;
constexpr int OFF_SGK = 11216;
constexpr int OFF_TH  = 11280;
constexpr int OFF_RED = 11344;
constexpr int SM_FLOATS = 11348;
constexpr int SM_BYTES  = SM_FLOATS * 4;   // 45392 B -> 5 CTAs/SM

// g_small layout
constexpr int GS_BOUT = 0;     // 28
constexpr int GS_WM1  = 32;    // 64
constexpr int GS_WM2B = 96;    // 64
constexpr int GS_BPCQ = 160;
constexpr int GS_BPCK = 161;
constexpr int GS_TOTAL = 176;

// W column blocks (permuted for single-float4 thread loads):
//  block1 (32 logical cols, cpos 0..7): c = cpos + 8*mm
//    c: 0..27 = M columns (y) | 28 sigma_q | 29 sigma_k | 30,31 pads
//    cp(c) = 4*(c % 8) + c/8
//  block2 (28 V' cols, cpos2 0..6): c2 = cpos2 + 7*mm, cp = 32 + 4*(c2%7) + c2/7
}

__device__ __align__(16) float g_WT[28 * STW];
__device__ __align__(16) float g_Wm2aT[64 * 64];   // [j][i]
__device__ __align__(16) float g_small[GS_TOTAL];
__constant__ __align__(16) float c_small[GS_TOTAL];

__global__ void __launch_bounds__(TPB) prep_kernel(
    const float* __restrict__ W_qk,   // [56,28]
    const float* __restrict__ W_v,    // [28,28]
    const float* __restrict__ W_out,  // [28,28]
    const float* __restrict__ W_m2a,  // [64,64]
    const float* __restrict__ b_out,  // [28]
    const float* __restrict__ W_pcq,  // [28]
    const float* __restrict__ b_pcq,  // [1]
    const float* __restrict__ W_pck,  // [28]
    const float* __restrict__ b_pck,  // [1]
    const float* __restrict__ W_m1,   // [64]
    const float* __restrict__ W_m2b)  // [64]
{
    const int gtid = blockIdx.x * TPB + threadIdx.x;
    const int gstep = gridDim.x * TPB;
    // M[e][f] = sum_r W_q[r][e] * W_k[r][f]  -> block1 col f
    for (int i = gtid; i < 784; i += gstep) {
        const int e = i / 28, f = i % 28;
        float acc = 0.f;
        #pragma unroll 7
        for (int r = 0; r < 28; r++)
            acc = fmaf(W_qk[r * 28 + e], W_qk[(28 + r) * 28 + f], acc);
        g_WT[e * STW + 4 * (f % 8) + (f / 8)] = acc;
    }
    // V' = W_out @ W_v  -> block2
    for (int i = gtid; i < 784; i += gstep) {
        const int c = i / 28, e = i % 28;
        float acc = 0.f;
        #pragma unroll 7
        for (int d = 0; d < 28; d++)
            acc = fmaf(W_out[c * 28 + d], W_v[d * 28 + e], acc);
        g_WT[e * STW + 32 + 4 * (c % 7) + (c / 7)] = acc;
    }
    // sigma columns (wx = W^T w_pc) + zero pads
    for (int i = gtid; i < 112; i += gstep) {
        const int e = i % 28, which = i / 28;
        if (which < 2) {
            const float* wp = (which == 0) ? W_pcq : W_pck;
            const int coff = (which == 0) ? 0 : 28;
            float acc = 0.f;
            #pragma unroll 7
            for (int c = 0; c < 28; c++)
                acc = fmaf(wp[c], W_qk[(coff + c) * 28 + e], acc);
            // cp(28)=4*4+3=19, cp(29)=4*5+3=23
            g_WT[e * STW + ((which == 0) ? 19 : 23)] = acc;
        } else {
            // pads: cp(30)=27, cp(31)=31
            g_WT[e * STW + ((which == 2) ? 27 : 31)] = 0.f;
        }
    }
    // W_m2a^T
    for (int i = gtid; i < 4096; i += gstep) {
        const int r = i >> 6, cc = i & 63;
        g_Wm2aT[cc * 64 + r] = W_m2a[i];
    }
    // pack small vectors
    if (blockIdx.x == 0) {
        const int t = threadIdx.x;
        if (t < 28) g_small[GS_BOUT + t] = b_out[t];
        else if (t < 92)  g_small[GS_WM1  + t - 28] = W_m1[t - 28];
        else if (t < 156) g_small[GS_WM2B + t - 92] = W_m2b[t - 92];
        else if (t == 156) g_small[GS_BPCQ] = b_pcq[0];
        else if (t == 157) g_small[GS_BPCK] = b_pck[0];
    }
}

__global__ void __launch_bounds__(TPB, 5) ipb_kernel(
    const float* __restrict__ x,
    float* __restrict__ out)
{
    extern __shared__ float sm[];
    float* sxT  = sm + OFF_XT;
    float* syT  = sm + OFF_YT;
    float* sWT  = sm + OFF_WT;
    float* sv   = sm + OFF_V;
    float* ssim = sm + OFF_SIM;
    float* satT = sm + OFF_AT;
    float* sigq = sm + OFF_SGQ;
    float* sigk = sm + OFF_SGK;
    float* sth  = sm + OFF_TH;
    float* sred = sm + OFF_RED;

    const int tid  = threadIdx.x;
    const int widx = blockIdx.x & 1023;
    const int Bi   = blockIdx.x >> 10;
    const int wh = widx >> 5, ww = widx & 31;
    const float* xbase = x + (size_t)Bi * B_STR + wh * 8 * H_STR + ww * 8 * 28;

    // ======== S0: x transpose + weight copy ========
    {
        {
            const int r = tid & 63, c4 = (tid >> 6) * 4;
            const float4 v = *(const float4*)(xbase + (r >> 3) * H_STR + (r & 7) * 28 + c4);
            sxT[(c4 + 0) * 64 + r] = v.x;
            sxT[(c4 + 1) * 64 + r] = v.y;
            sxT[(c4 + 2) * 64 + r] = v.z;
            sxT[(c4 + 3) * 64 + r] = v.w;
        }
        if (tid < 192) {
            const int i = tid + 256;
            const int r = i & 63, c4 = (i >> 6) * 4;
            const float4 v = *(const float4*)(xbase + (r >> 3) * H_STR + (r & 7) * 28 + c4);
            sxT[(c4 + 0) * 64 + r] = v.x;
            sxT[(c4 + 1) * 64 + r] = v.y;
            sxT[(c4 + 2) * 64 + r] = v.z;
            sxT[(c4 + 3) * 64 + r] = v.w;
        }
        ((float4*)sWT)[tid] = ((const float4*)g_WT)[tid];
        if (tid < 164)
            ((float4*)sWT)[tid + 256] = ((const float4*)g_WT)[tid + 256];
    }
    __syncthreads();

    // ======== S1: [y | sigma | V'] = x @ [M | wx | W_vo^T] ========
    // 240 units: u<128 block1 (t-fast), u>=128 block2 (V, cpos-fast)
    if (tid < 240) {
        if (tid < 128) {
            const int t16 = tid & 15, cpos = tid >> 4;   // cpos 0..7
            const int t4 = t16 * 4;
            const float* xb = sxT + t4;
            const float* wb = sWT + 4 * cpos;
            float4 acc[4] = {{0,0,0,0},{0,0,0,0},{0,0,0,0},{0,0,0,0}};
            #pragma unroll
            for (int k = 0; k < 28; k++) {
                const float4 a = *(const float4*)&xb[k * 64];
                const float4 w = *(const float4*)&wb[k * STW];
                #pragma unroll
                for (int mm = 0; mm < 4; mm++) {
                    const float wv = (mm == 0) ? w.x : (mm == 1) ? w.y : (mm == 2) ? w.z : w.w;
                    acc[mm].x = fmaf(a.x, wv, acc[mm].x);
                    acc[mm].y = fmaf(a.y, wv, acc[mm].y);
                    acc[mm].z = fmaf(a.z, wv, acc[mm].z);
                    acc[mm].w = fmaf(a.w, wv, acc[mm].w);
                }
            }
            #pragma unroll
            for (int mm = 0; mm < 4; mm++) {
                const int c = cpos + 8 * mm;
                const float* fa = (const float*)&acc[mm];
                if (c < 28) {
                    *(float4*)&syT[c * 64 + 4 * ((t16 ^ c) & 15)] = acc[mm];
                } else if (c == 28) {
                    const float bq = c_small[GS_BPCQ];
                    #pragma unroll
                    for (int tt = 0; tt < 4; tt++) sigq[t4 + tt] = fa[tt] + bq;
                } else if (c == 29) {
                    const float bk = c_small[GS_BPCK];
                    #pragma unroll
                    for (int tt = 0; tt < 4; tt++) sigk[t4 + tt] = fa[tt] + bk;
                }
            }
        } else {
            const int v = tid - 128;                     // 0..111
            const int cpos2 = v % 7, tg = v / 7;         // tg 0..15
            const int t4 = tg * 4;
            const float* xb = sxT + t4;
            const float* wb = sWT + 32 + 4 * cpos2;
            float4 acc[4] = {{0,0,0,0},{0,0,0,0},{0,0,0,0},{0,0,0,0}};
            #pragma unroll
            for (int k = 0; k < 28; k++) {
                const float4 a = *(const float4*)&xb[k * 64];
                const float4 w = *(const float4*)&wb[k * STW];
                #pragma unroll
                for (int mm = 0; mm < 4; mm++) {
                    const float wv = (mm == 0) ? w.x : (mm == 1) ? w.y : (mm == 2) ? w.z : w.w;
                    acc[mm].x = fmaf(a.x, wv, acc[mm].x);
                    acc[mm].y = fmaf(a.y, wv, acc[mm].y);
                    acc[mm].z = fmaf(a.z, wv, acc[mm].z);
                    acc[mm].w = fmaf(a.w, wv, acc[mm].w);
                }
            }
            #pragma unroll
            for (int mm = 0; mm < 4; mm++) {
                const int d0 = cpos2 + 7 * mm;
                const float* fa = (const float*)&acc[mm];
                #pragma unroll
                for (int tt = 0; tt < 4; tt++)
                    sv[(t4 + tt) * 28 + d0] = fa[tt];
            }
        }
    }
    __syncthreads();

    // ======== S2: sim = y @ x^T (256 threads, 4x4) ========
    {
        const int t4 = (tid >> 4) * 4;
        const int j4 = (tid & 15) * 4;
        const int tq = t4 >> 2;
        float4 acc[4] = {{0,0,0,0},{0,0,0,0},{0,0,0,0},{0,0,0,0}};
        #pragma unroll
        for (int k = 0; k < 28; k++) {
            const float4 q  = *(const float4*)&syT[k * 64 + 4 * ((tq ^ k) & 15)];
            const float4 kk = *(const float4*)&sxT[k * 64 + j4];
            #pragma unroll
            for (int tt = 0; tt < 4; tt++) {
                const float qv = (tt == 0) ? q.x : (tt == 1) ? q.y : (tt == 2) ? q.z : q.w;
                acc[tt].x = fmaf(qv, kk.x, acc[tt].x);
                acc[tt].y = fmaf(qv, kk.y, acc[tt].y);
                acc[tt].z = fmaf(qv, kk.z, acc[tt].z);
                acc[tt].w = fmaf(qv, kk.w, acc[tt].w);
            }
        }
        const int jq = j4 >> 2;
        #pragma unroll
        for (int tt = 0; tt < 4; tt++) {
            const int r = t4 + tt;
            *(float4*)&ssim[r * 64 + 4 * ((jq ^ (r & 15)) & 15)] = acc[tt];
        }
    }
    __syncthreads();

    // ======== S3: theta_raw[i] = sum_{j!=i} sim[i,j] * W_m1[j] ========
    if (tid < 64) {
        const int r = tid, rx = r & 15;
        const float* srow = ssim + r * 64;
        float acc = 0.f;
        #pragma unroll
        for (int j4 = 0; j4 < 64; j4 += 4) {
            const float4 s = *(const float4*)&srow[4 * (((j4 >> 2) ^ rx) & 15)];
            const float4 w = *(const float4*)&c_small[GS_WM1 + j4];
            acc = fmaf(s.x, w.x, acc); acc = fmaf(s.y, w.y, acc);
            acc = fmaf(s.z, w.z, acc); acc = fmaf(s.w, w.w, acc);
        }
        const float diag = srow[4 * (((r >> 2) ^ rx) & 15) + (r & 3)];
        acc -= diag * g_small[GS_WM1 + r];   // divergent -> LDG
        sth[r] = acc;
    }
    __syncthreads();

    // ======== S4: theta = W_m2b . LeakyReLU(W_m2a @ theta_raw) ========
    {
        float* scratch = satT;   // xT/yT region, dead after S2
        const int i = tid & 63, part = tid >> 6;
        const float* col = g_Wm2aT + part * 16 * 64 + i;
        const float* thp = sth + part * 16;
        float acc = 0.f;
        #pragma unroll
        for (int jj = 0; jj < 16; jj++)
            acc = fmaf(col[jj * 64], thp[jj], acc);
        scratch[part * 64 + i] = acc;
        __syncthreads();
        if (tid < 64) {
            float t = scratch[tid] + scratch[64 + tid] + scratch[128 + tid] + scratch[192 + tid];
            t = (t >= 0.f) ? t : 0.1f * t;
            float val = t * g_small[GS_WM2B + tid];   // divergent -> LDG
            #pragma unroll
            for (int o = 16; o > 0; o >>= 1)
                val += __shfl_down_sync(0xffffffffu, val, o);
            if ((tid & 31) == 0) sred[tid >> 5] = val;
        }
        __syncthreads();
    }
    const float theta = sred[0] + sred[1];

    // ======== S5: softmax, 8 lanes/row; attn transposed+swizzled ========
    // satT[j][t] at j*64 + 4*(((t>>2) ^ (j>>3)) & 15) + (t&3)
    {
        const int sub = tid & 7;
        const int rg  = tid >> 3;
        const float4 k0 = *(const float4*)&sigk[sub * 8];
        const float4 k1 = *(const float4*)&sigk[sub * 8 + 4];
        #pragma unroll
        for (int pass = 0; pass < 2; pass++) {
            const int r = rg + pass * 32;
            const int rx = r & 15;
            const float sgq = sigq[r];
            const float4 v0 = *(const float4*)&ssim[r * 64 + 4 * (((sub * 2) ^ rx) & 15)];
            const float4 v1 = *(const float4*)&ssim[r * 64 + 4 * (((sub * 2 + 1) ^ rx) & 15)];
            float s[8];
            s[0] = v0.x * (sgq * k0.x); s[1] = v0.y * (sgq * k0.y);
            s[2] = v0.z * (sgq * k0.z); s[3] = v0.w * (sgq * k0.w);
            s[4] = v1.x * (sgq * k1.x); s[5] = v1.y * (sgq * k1.y);
            s[6] = v1.z * (sgq * k1.z); s[7] = v1.w * (sgq * k1.w);
            float m = fmaxf(fmaxf(fmaxf(s[0], s[1]), fmaxf(s[2], s[3])),
                            fmaxf(fmaxf(s[4], s[5]), fmaxf(s[6], s[7])));
            m = fmaxf(m, __shfl_xor_sync(0xffffffffu, m, 1));
            m = fmaxf(m, __shfl_xor_sync(0xffffffffu, m, 2));
            m = fmaxf(m, __shfl_xor_sync(0xffffffffu, m, 4));
            float e[8];
            #pragma unroll
            for (int u = 0; u < 8; u++) e[u] = __expf(s[u] - m);
            float ss = ((e[0] + e[1]) + (e[2] + e[3])) + ((e[4] + e[5]) + (e[6] + e[7]));
            ss += __shfl_xor_sync(0xffffffffu, ss, 1);
            ss += __shfl_xor_sync(0xffffffffu, ss, 2);
            ss += __shfl_xor_sync(0xffffffffu, ss, 4);
            const float inv = 1.0f / ss;
            // j = sub*8 + jj  ->  j>>3 == sub
            float* sbase = satT + (sub * 8) * 64 + 4 * (((r >> 2) ^ sub) & 15) + (r & 3);
            #pragma unroll
            for (int jj = 0; jj < 8; jj++)
                sbase[jj * 64] = (s[jj] > theta) ? e[jj] * inv : 0.f;
        }
    }
    __syncthreads();

    // ======== S6: out = attn @ V' + b_out. 112 threads, 4t x 4d ========
    if (tid < 112) {
        const int tgrp = tid / 7, dpos = tid % 7;
        const int t4 = tgrp * 4, d4 = dpos * 4;
        const float* vb = sv + d4;
        float4 acc[4] = {{0,0,0,0},{0,0,0,0},{0,0,0,0},{0,0,0,0}};
        #pragma unroll
        for (int j = 0; j < 64; j++) {
            const float4 at = *(const float4*)&satT[j * 64 + 4 * ((tgrp ^ (j >> 3)) & 15)];
            const float4 vv = *(const float4*)&vb[j * 28];
            #pragma unroll
            for (int tt = 0; tt < 4; tt++) {
                const float av = (tt == 0) ? at.x : (tt == 1) ? at.y : (tt == 2) ? at.z : at.w;
                acc[tt].x = fmaf(av, vv.x, acc[tt].x);
                acc[tt].y = fmaf(av, vv.y, acc[tt].y);
                acc[tt].z = fmaf(av, vv.z, acc[tt].z);
                acc[tt].w = fmaf(av, vv.w, acc[tt].w);
            }
        }
        const float4 bb = *(const float4*)&g_small[GS_BOUT + d4];   // LDG
        #pragma unroll
        for (int tt = 0; tt < 4; tt++) {
            const int t = t4 + tt;
            float* ob = out + (size_t)Bi * B_STR + (wh * 8 + (t >> 3)) * H_STR
                        + (ww * 8 + (t & 7)) * 28 + d4;
            *(float4*)ob = make_float4(acc[tt].x + bb.x, acc[tt].y + bb.y,
                                       acc[tt].z + bb.z, acc[tt].w + bb.w);
        }
    }
}

extern "C" void kernel_launch(void* const* d_in, const int* in_sizes, int n_in,
                              void* d_out, int out_size) {
    (void)in_sizes; (void)n_in; (void)out_size;
    cudaFuncSetAttribute(ipb_kernel, cudaFuncAttributeMaxDynamicSharedMemorySize, SM_BYTES);
    prep_kernel<<<16, TPB>>>(
        (const float*)d_in[1],   // W_qk
        (const float*)d_in[2],   // W_v
        (const float*)d_in[3],   // W_out
        (const float*)d_in[10],  // W_m2a
        (const float*)d_in[4],   // b_out
        (const float*)d_in[5],   // W_pcq
        (const float*)d_in[6],   // b_pcq
        (const float*)d_in[7],   // W_pck
        (const float*)d_in[8],   // b_pck
        (const float*)d_in[9],   // W_m1
        (const float*)d_in[11]); // W_m2b
    void* gsp = nullptr;
    cudaGetSymbolAddress(&gsp, g_small);
    cudaMemcpyToSymbolAsync(c_small, gsp, GS_TOTAL * 4, 0, cudaMemcpyDeviceToDevice, 0);
    ipb_kernel<<<8192, TPB, SM_BYTES>>>(
        (const float*)d_in[0],   // x
        (float*)d_out);
}